// round 15
// baseline (speedup 1.0000x reference)
#include <cuda_runtime.h>
#include <cuda_fp16.h>
#include <math.h>
#include <stdint.h>

#define BATCH 8
#define SEQ 1213
#define NHEAD 12
#define DHEAD 64
#define HIDDIM 768
#define INTERDIM 3072
#define MROWS (BATCH*SEQ)      // 9704
#define NLEAD 12

// ---------------- scratch (static device globals; no allocation allowed) ----
__device__ float  g_q[(size_t)BATCH*NHEAD*SEQ*DHEAD];
__device__ float  g_k[(size_t)BATCH*NHEAD*SEQ*DHEAD];
__device__ float  g_v[(size_t)BATCH*NHEAD*SEQ*DHEAD];
__device__ __half g_ctx16[(size_t)MROWS*HIDDIM];
__device__ float  g_t1[(size_t)MROWS*HIDDIM];
__device__ float  g_attn[(size_t)MROWS*HIDDIM];
__device__ __half g_attn16[(size_t)MROWS*HIDDIM];
__device__ __half g_inter16[(size_t)MROWS*INTERDIM];
__device__ float  g_t2[(size_t)MROWS*HIDDIM];
__device__ __half g_hs16[(size_t)MROWS*HIDDIM];
// transposed fp16 weights [N][K]
__device__ __half g_wqt[(size_t)HIDDIM*HIDDIM];
__device__ __half g_wkt[(size_t)HIDDIM*HIDDIM];
__device__ __half g_wvt[(size_t)HIDDIM*HIDDIM];
__device__ __half g_wot[(size_t)HIDDIM*HIDDIM];
__device__ __half g_wit[(size_t)INTERDIM*HIDDIM];
__device__ __half g_wdt[(size_t)HIDDIM*INTERDIM];

// ---------------- helpers ----------------------------------------------------
__device__ __forceinline__ void mma_tf32(float* c, const unsigned* a, const unsigned* b) {
    asm("mma.sync.aligned.m16n8k8.row.col.f32.tf32.tf32.f32 "
        "{%0,%1,%2,%3}, {%4,%5,%6,%7}, {%8,%9}, {%0,%1,%2,%3};"
        : "+f"(c[0]), "+f"(c[1]), "+f"(c[2]), "+f"(c[3])
        : "r"(a[0]), "r"(a[1]), "r"(a[2]), "r"(a[3]), "r"(b[0]), "r"(b[1]));
}
__device__ __forceinline__ void mma_f16(float* c, const unsigned* a, const unsigned* b) {
    asm("mma.sync.aligned.m16n8k16.row.col.f32.f16.f16.f32 "
        "{%0,%1,%2,%3}, {%4,%5,%6,%7}, {%8,%9}, {%0,%1,%2,%3};"
        : "+f"(c[0]), "+f"(c[1]), "+f"(c[2]), "+f"(c[3])
        : "r"(a[0]), "r"(a[1]), "r"(a[2]), "r"(a[3]), "r"(b[0]), "r"(b[1]));
}
__device__ __forceinline__ void ldsm_x4(unsigned& r0, unsigned& r1, unsigned& r2,
                                        unsigned& r3, uint32_t addr) {
    asm volatile("ldmatrix.sync.aligned.m8n8.x4.shared.b16 {%0,%1,%2,%3}, [%4];"
                 : "=r"(r0), "=r"(r1), "=r"(r2), "=r"(r3) : "r"(addr));
}
__device__ __forceinline__ uint32_t smem_u32(const void* p) {
    return (uint32_t)__cvta_generic_to_shared(p);
}
__device__ __forceinline__ void cp16(uint32_t dst, const void* src, int src_bytes) {
    asm volatile("cp.async.cg.shared.global [%0], [%1], 16, %2;"
                 :: "r"(dst), "l"(src), "r"(src_bytes) : "memory");
}
#define CP_COMMIT() asm volatile("cp.async.commit_group;" ::: "memory")
#define CP_WAIT1()  asm volatile("cp.async.wait_group 1;" ::: "memory")
#define CP_WAIT0()  asm volatile("cp.async.wait_group 0;" ::: "memory")

// ============================================================================
// fp32 -> fp16 convert (n multiple of 4)
// ============================================================================
__global__ __launch_bounds__(256)
void f2h_kernel(const float* __restrict__ x, __half* __restrict__ y, int n)
{
    const int i = (blockIdx.x * 256 + threadIdx.x) * 4;
    if (i < n) {
        const float4 v = *reinterpret_cast<const float4*>(x + i);
        __half2* yp = reinterpret_cast<__half2*>(y + i);
        yp[0] = __floats2half2_rn(v.x, v.y);
        yp[1] = __floats2half2_rn(v.z, v.w);
    }
}

// ============================================================================
// Weight transpose + fp16 convert: dst[c][r] = (half)src[r][c]
// ============================================================================
struct TransArgs { const float* src[4]; __half* dst[4]; };

__global__ __launch_bounds__(256)
void transpose_kernel(TransArgs ta, int R, int C)
{
    __shared__ float t[32][33];
    const float* src = ta.src[blockIdx.z];
    __half* dst = ta.dst[blockIdx.z];
    const int bx = blockIdx.x * 32, by = blockIdx.y * 32;
    const int tx = threadIdx.x & 31, ty = threadIdx.x >> 5;  // 32 x 8
#pragma unroll
    for (int i = ty; i < 32; i += 8)
        t[i][tx] = src[(size_t)(by + i) * C + bx + tx];
    __syncthreads();
#pragma unroll
    for (int i = ty; i < 32; i += 8)
        dst[(size_t)(bx + i) * R + by + tx] = __float2half_rn(t[tx][i]);
}

// ============================================================================
// FP16 tensor-core GEMM: C[M,N] = A16[M,K] @ Wt16[N,K]^T (+epilogue)
// BM=BN=128, BK=32, 256 threads (8 warps 2x4), warp tile 64x32,
// mma.m16n8k16 f16/f32-acc, ldmatrix fragment loads, 3-stage cp.async ring.
// SMEM tiles: A [128 rows][40 halves] (80B stride, ldmatrix conflict-free),
//             B [128 rows][40 halves]; one stage = 20480 B.
// ============================================================================
#define HBM 128
#define HBN 128
#define HBK 32
#define HSTRIDE_B 80            // bytes per smem row
#define HTILE_B (128*HSTRIDE_B) // 10240
#define HSTAGE_B (2*HTILE_B)    // 20480 (A then B)
#define HSTAGES 3
#define HGEMM_SMEM (HSTAGES*HSTAGE_B)   // 61440

enum { MODE_QKV = 0, MODE_RES = 1, MODE_GELU = 2 };

struct GemmArgs {
    const __half* W[3];     // transposed fp16 weights [N][K]
    const float*  bias[3];
    void*         out[3];   // float* (QKV/RES) or __half* (GELU)
};

template<int MODE>
__global__ __launch_bounds__(256, 2)
void hgemm_kernel(const __half* __restrict__ A, GemmArgs ga,
                  const float* __restrict__ Rsd, int K, int N)
{
    extern __shared__ char smc[];
    const uint32_t sb = smem_u32(smc);

    const int tid  = threadIdx.x;
    const int warp = tid >> 5;
    const int lane = tid & 31;
    const int wm   = warp >> 2;        // 0..1
    const int wn   = warp & 3;         // 0..3
    const int g    = lane >> 2;
    const int t4   = lane & 3;
    const int m0   = blockIdx.x * HBM;
    const int n0   = blockIdx.y * HBN;
    const int z    = blockIdx.z;

    const __half* W    = ga.W[z];
    const float*  bias = ga.bias[z];

    float acc[4][4][4];
#pragma unroll
    for (int i = 0; i < 4; i++)
#pragma unroll
        for (int j = 0; j < 4; j++)
#pragma unroll
            for (int r = 0; r < 4; r++) acc[i][j][r] = 0.f;

    // stage one K-chunk: A 128x32 halves + B 128x32 halves
    auto stage = [&](int kt, int s) {
        const int k0 = kt * HBK;
        const uint32_t ab = sb + s * HSTAGE_B;
        const uint32_t bb = ab + HTILE_B;
#pragma unroll
        for (int p = 0; p < 2; p++) {
            const int idx = tid + p * 256;      // 512 granules per tile
            const int r = idx >> 2, cq = idx & 3;
            cp16(ab + r * HSTRIDE_B + cq * 16,
                 A + (size_t)(m0 + r) * K + k0 + cq * 8, (m0 + r < MROWS) ? 16 : 0);
            cp16(bb + r * HSTRIDE_B + cq * 16,
                 W + (size_t)(n0 + r) * K + k0 + cq * 8, 16);
        }
    };

    const int nkt = K / HBK;           // 24 or 96
    stage(0, 0); CP_COMMIT();
    stage(1, 1); CP_COMMIT();

    // per-lane ldmatrix offsets
    // A: matrices (rows +0-7, k-lo), (rows +8-15, k-lo), (rows +0-7, k-hi), (+8-15, k-hi)
    const uint32_t aoff = (uint32_t)(wm * 64 + ((lane >> 3) & 1) * 8 + (lane & 7)) * HSTRIDE_B
                        + ((lane >> 4) & 1) * 16;
    // B: matrices (j0, k-lo), (j0, k-hi), (j1, k-lo), (j1, k-hi); rows = n
    const int bm = lane >> 3;          // 0..3
    const uint32_t boff = (uint32_t)(wn * 32 + (bm >> 1) * 8 + (lane & 7)) * HSTRIDE_B
                        + (bm & 1) * 16;

    int buf = 0;
    for (int kt = 0; kt < nkt; kt++) {
        CP_WAIT1();
        __syncthreads();
        if (kt + 2 < nkt) stage(kt + 2, (kt + 2) % HSTAGES);
        CP_COMMIT();

        const uint32_t ab = sb + buf * HSTAGE_B;
        const uint32_t bb = ab + HTILE_B;

#pragma unroll
        for (int kk = 0; kk < 2; kk++) {       // two k16 chunks (byte offset kk*32)
            unsigned a[4][4], b[4][2];
#pragma unroll
            for (int i = 0; i < 4; i++)
                ldsm_x4(a[i][0], a[i][1], a[i][2], a[i][3],
                        ab + aoff + i * (16 * HSTRIDE_B) + kk * 32);
            ldsm_x4(b[0][0], b[0][1], b[1][0], b[1][1], bb + boff + kk * 32);
            ldsm_x4(b[2][0], b[2][1], b[3][0], b[3][1],
                    bb + boff + 16 * HSTRIDE_B + kk * 32);
#pragma unroll
            for (int i = 0; i < 4; i++)
#pragma unroll
                for (int j = 0; j < 4; j++)
                    mma_f16(acc[i][j], a[i], b[j]);
        }
        buf = (buf + 1 == HSTAGES) ? 0 : buf + 1;
    }

    // ---- epilogue ----
#pragma unroll
    for (int i = 0; i < 4; i++) {
#pragma unroll
        for (int rr = 0; rr < 2; rr++) {
            const int m = m0 + wm * 64 + i * 16 + g + rr * 8;
            if (m >= MROWS) continue;
#pragma unroll
            for (int j = 0; j < 4; j++) {
                const int n = n0 + wn * 32 + j * 8 + t4 * 2;
                const float2 b2 = *reinterpret_cast<const float2*>(bias + n);
                const float x0 = acc[i][j][rr * 2 + 0] + b2.x;
                const float x1 = acc[i][j][rr * 2 + 1] + b2.y;

                if (MODE == MODE_QKV) {
                    float* out = (float*)ga.out[z];
                    const int h = n >> 6, d = n & 63;
                    const int bb2 = m / SEQ, srow = m % SEQ;
                    *reinterpret_cast<float2*>(
                        out + (((size_t)bb2 * NHEAD + h) * SEQ + srow) * DHEAD + d) =
                        make_float2(x0, x1);
                } else if (MODE == MODE_RES) {
                    float* out = (float*)ga.out[z];
                    const float2 r2 = *reinterpret_cast<const float2*>(Rsd + (size_t)m * N + n);
                    *reinterpret_cast<float2*>(out + (size_t)m * N + n) =
                        make_float2(x0 + r2.x, x1 + r2.y);
                } else {    // MODE_GELU -> fp16 output
                    __half* out = (__half*)ga.out[z];
                    float o0 = 0.5f * x0 * (1.f + erff(x0 * 0.70710678118654752f));
                    float o1 = 0.5f * x1 * (1.f + erff(x1 * 0.70710678118654752f));
                    *reinterpret_cast<__half2*>(out + (size_t)m * N + n) =
                        __floats2half2_rn(o0, o1);
                }
            }
        }
    }
}

// ============================================================================
// Flash attention: tf32 mma.sync (unchanged numerics from R9);
// epilogue writes fp16 ctx for the O-projection.
// ============================================================================
#define AQT 128
#define AKT 64
#define KPAD 68
#define VPAD 72
#define PPAD 68
#define FLASH_SMEM ((2*AKT*KPAD + 2*AKT*VPAD + AQT*PPAD) * 4)   // 106496

__global__ __launch_bounds__(256, 2)
void flash_attn_kernel(const float* __restrict__ Q, const float* __restrict__ Kg,
                       const float* __restrict__ Vg, const float* __restrict__ amask,
                       __half* __restrict__ ctx)
{
    extern __shared__ float sm[];
    float* sK = sm;                        // [2][64][KPAD]
    float* sV = sK + 2 * AKT * KPAD;       // [2][64][VPAD]
    float* sP = sV + 2 * AKT * VPAD;       // [128][PPAD]

    const int tid  = threadIdx.x;
    const int warp = tid >> 5;
    const int lane = tid & 31;
    const int g    = lane >> 2;
    const int t4   = lane & 3;
    const int qb   = warp * 16;
    const int q0   = blockIdx.x * AQT;
    const int h    = blockIdx.y;
    const int b    = blockIdx.z;
    const size_t base = ((size_t)b * NHEAD + h) * SEQ * DHEAD;

#pragma unroll
    for (int p = 0; p < 8; p++) {
        const int row = (tid >> 4) + p * 16;
        const int col = (tid & 15) * 4;
        float4 v = make_float4(0.f, 0.f, 0.f, 0.f);
        if (q0 + row < SEQ)
            v = *reinterpret_cast<const float4*>(Q + base + (size_t)(q0 + row) * DHEAD + col);
        *reinterpret_cast<float4*>(&sP[row * PPAD + col]) = v;
    }
    __syncthreads();

    unsigned qf[8][4];
#pragma unroll
    for (int kk = 0; kk < 8; kk++) {
        const float* qr = &sP[(qb + g) * PPAD + kk * 8 + t4];
        qf[kk][0] = __float_as_uint(qr[0]);
        qf[kk][1] = __float_as_uint(qr[8 * PPAD]);
        qf[kk][2] = __float_as_uint(qr[4]);
        qf[kk][3] = __float_as_uint(qr[8 * PPAD + 4]);
    }

    float m_run[2] = {-1e30f, -1e30f};
    float l_run[2] = {0.f, 0.f};
    float o[8][4];
#pragma unroll
    for (int j = 0; j < 8; j++)
#pragma unroll
        for (int r = 0; r < 4; r++) o[j][r] = 0.f;

    const bool lead_warp = (q0 == 0 && warp == 0);
    const int nkt = (SEQ + AKT - 1) / AKT;   // 19

    auto stageKV = [&](int kt, int buf) {
        const int k0 = kt * AKT;
        float* Kb = sK + buf * AKT * KPAD;
        float* Vb = sV + buf * AKT * VPAD;
#pragma unroll
        for (int p = 0; p < 4; p++) {
            const int s = tid + p * 256;
            const int row = s >> 4, c = (s & 15) * 4;
            const int sz = (k0 + row < SEQ) ? 16 : 0;
            const size_t off = base + (size_t)(k0 + row) * DHEAD + c;
            cp16(smem_u32(Kb + row * KPAD + c), Kg + off, sz);
            cp16(smem_u32(Vb + row * VPAD + c), Vg + off, sz);
        }
    };

    stageKV(0, 0); CP_COMMIT();

    for (int kt = 0; kt < nkt; kt++) {
        const int k0 = kt * AKT;
        const int buf = kt & 1;
        CP_WAIT0();
        __syncthreads();

        if (kt + 1 < nkt) stageKV(kt + 1, buf ^ 1);
        CP_COMMIT();

        const float* Kb = sK + buf * AKT * KPAD;
        const float* Vb = sV + buf * AKT * VPAD;

        float sc[8][4];
#pragma unroll
        for (int j = 0; j < 8; j++)
#pragma unroll
            for (int r = 0; r < 4; r++) sc[j][r] = 0.f;

#pragma unroll
        for (int kk = 0; kk < 8; kk++) {
#pragma unroll
            for (int j = 0; j < 8; j++) {
                unsigned bb[2];
                const float* kr = &Kb[(j * 8 + g) * KPAD + kk * 8 + t4];
                bb[0] = __float_as_uint(kr[0]);
                bb[1] = __float_as_uint(kr[4]);
                mma_tf32(sc[j], qf[kk], bb);
            }
        }

#pragma unroll
        for (int j = 0; j < 8; j++) {
#pragma unroll
            for (int e = 0; e < 2; e++) {
                const int cg = k0 + j * 8 + 2 * t4 + e;
                const float am = (cg < SEQ) ? __ldg(amask + (size_t)b * SEQ + cg) : 0.f;
#pragma unroll
                for (int rr = 0; rr < 2; rr++) {
                    float val = fmaf(sc[j][rr * 2 + e], 0.125f, am);
                    if (cg >= SEQ) val = -1e30f;
                    if (lead_warp) {
                        const int qg = qb + g + rr * 8;
                        if (qg == 0) {
                            if (cg >= 1 && cg < 1 + NLEAD) val -= 99999.f;
                        } else if (qg >= 1 && qg <= NLEAD) {
                            const int start = NLEAD + 1 + 100 * (qg - 1);
                            if (!(cg >= start && cg < start + 100)) val -= 99999.f;
                        }
                    }
                    sc[j][rr * 2 + e] = val;
                }
            }
        }

#pragma unroll
        for (int rr = 0; rr < 2; rr++) {
            float mt = -1e30f;
#pragma unroll
            for (int j = 0; j < 8; j++)
                mt = fmaxf(mt, fmaxf(sc[j][rr * 2], sc[j][rr * 2 + 1]));
            mt = fmaxf(mt, __shfl_xor_sync(0xffffffffu, mt, 1));
            mt = fmaxf(mt, __shfl_xor_sync(0xffffffffu, mt, 2));
            const float mnew = fmaxf(m_run[rr], mt);
            const float fac = __expf(m_run[rr] - mnew);
            m_run[rr] = mnew;
            float ls = 0.f;
#pragma unroll
            for (int j = 0; j < 8; j++) {
                const float p0 = __expf(sc[j][rr * 2    ] - mnew);
                const float p1 = __expf(sc[j][rr * 2 + 1] - mnew);
                sc[j][rr * 2    ] = p0;
                sc[j][rr * 2 + 1] = p1;
                ls += p0 + p1;
            }
            ls += __shfl_xor_sync(0xffffffffu, ls, 1);
            ls += __shfl_xor_sync(0xffffffffu, ls, 2);
            l_run[rr] = l_run[rr] * fac + ls;
#pragma unroll
            for (int j = 0; j < 8; j++) {
                o[j][rr * 2    ] *= fac;
                o[j][rr * 2 + 1] *= fac;
            }
        }

#pragma unroll
        for (int rr = 0; rr < 2; rr++)
#pragma unroll
            for (int j = 0; j < 8; j++)
                *reinterpret_cast<float2*>(
                    &sP[(qb + g + rr * 8) * PPAD + j * 8 + 2 * t4]) =
                    make_float2(sc[j][rr * 2], sc[j][rr * 2 + 1]);
        __syncwarp();

#pragma unroll
        for (int kk = 0; kk < 8; kk++) {
            unsigned a[4];
            const float* pr = &sP[(qb + g) * PPAD + kk * 8 + t4];
            a[0] = __float_as_uint(pr[0]);
            a[1] = __float_as_uint(pr[8 * PPAD]);
            a[2] = __float_as_uint(pr[4]);
            a[3] = __float_as_uint(pr[8 * PPAD + 4]);
#pragma unroll
            for (int j = 0; j < 8; j++) {
                unsigned bb[2];
                const float* vr = &Vb[(kk * 8 + t4) * VPAD + j * 8 + g];
                bb[0] = __float_as_uint(vr[0]);
                bb[1] = __float_as_uint(vr[4 * VPAD]);
                mma_tf32(o[j], a, bb);
            }
        }
    }

    // ---- epilogue: normalize and write fp16 ctx [B,S,HID] ----
#pragma unroll
    for (int rr = 0; rr < 2; rr++) {
        const int qg = q0 + qb + g + rr * 8;
        if (qg < SEQ) {
            const float inv = 1.f / l_run[rr];
#pragma unroll
            for (int j = 0; j < 8; j++) {
                *reinterpret_cast<__half2*>(
                    ctx + ((size_t)b * SEQ + qg) * HIDDIM + h * DHEAD + j * 8 + 2 * t4) =
                    __floats2half2_rn(o[j][rr * 2] * inv, o[j][rr * 2 + 1] * inv);
            }
        }
    }
}

// ---------------- LayerNorm (fp32 out + optional fp16 copy) ------------------
__global__ __launch_bounds__(256)
void layernorm_kernel(const float* __restrict__ x, const float* __restrict__ g,
                      const float* __restrict__ bb, float* __restrict__ y,
                      __half* __restrict__ y16)
{
    __shared__ float red[8];
    __shared__ float sMean, sRstd;
    const int row = blockIdx.x;
    const int tid = threadIdx.x;
    const float* xr = x + (size_t)row * HIDDIM;

    float v[3];
    float sum = 0.f;
#pragma unroll
    for (int i = 0; i < 3; i++) { v[i] = xr[tid + i * 256]; sum += v[i]; }

#pragma unroll
    for (int o = 16; o > 0; o >>= 1) sum += __shfl_down_sync(0xffffffffu, sum, o);
    if ((tid & 31) == 0) red[tid >> 5] = sum;
    __syncthreads();
    if (tid < 32) {
        float t = (tid < 8) ? red[tid] : 0.f;
#pragma unroll
        for (int o = 4; o > 0; o >>= 1) t += __shfl_down_sync(0xffffffffu, t, o);
        if (tid == 0) sMean = t * (1.f / HIDDIM);
    }
    __syncthreads();
    const float mean = sMean;

    float sq = 0.f;
#pragma unroll
    for (int i = 0; i < 3; i++) { float d = v[i] - mean; sq += d * d; }
#pragma unroll
    for (int o = 16; o > 0; o >>= 1) sq += __shfl_down_sync(0xffffffffu, sq, o);
    __syncthreads();
    if ((tid & 31) == 0) red[tid >> 5] = sq;
    __syncthreads();
    if (tid < 32) {
        float t = (tid < 8) ? red[tid] : 0.f;
#pragma unroll
        for (int o = 4; o > 0; o >>= 1) t += __shfl_down_sync(0xffffffffu, t, o);
        if (tid == 0) sRstd = rsqrtf(t * (1.f / HIDDIM) + 1e-12f);
    }
    __syncthreads();
    const float rstd = sRstd;

#pragma unroll
    for (int i = 0; i < 3; i++) {
        const int c = tid + i * 256;
        const float val = g[c] * (v[i] - mean) * rstd + bb[c];
        y[(size_t)row * HIDDIM + c] = val;
        if (y16) y16[(size_t)row * HIDDIM + c] = __float2half_rn(val);
    }
}

// ---------------- launch ----------------------------------------------------
extern "C" void kernel_launch(void* const* d_in, const int* in_sizes, int n_in,
                              void* d_out, int out_size)
{
    const float* hs    = (const float*)d_in[0];
    const float* amask = (const float*)d_in[1];
    const float* Wq = (const float*)d_in[2];  const float* bq = (const float*)d_in[3];
    const float* Wk = (const float*)d_in[4];  const float* bk = (const float*)d_in[5];
    const float* Wv = (const float*)d_in[6];  const float* bv = (const float*)d_in[7];
    const float* Wo = (const float*)d_in[8];  const float* bo = (const float*)d_in[9];
    const float* g1 = (const float*)d_in[10]; const float* b1 = (const float*)d_in[11];
    const float* Wi = (const float*)d_in[12]; const float* bi = (const float*)d_in[13];
    const float* Wd = (const float*)d_in[14]; const float* bd = (const float*)d_in[15];
    const float* g2 = (const float*)d_in[16]; const float* b2 = (const float*)d_in[17];
    float* out = (float*)d_out;

    float *q, *k, *v, *t1, *attn, *t2;
    __half *ctx16, *attn16, *inter16, *hs16;
    __half *wqt, *wkt, *wvt, *wot, *wit, *wdt;
    cudaGetSymbolAddress((void**)&q,       g_q);
    cudaGetSymbolAddress((void**)&k,       g_k);
    cudaGetSymbolAddress((void**)&v,       g_v);
    cudaGetSymbolAddress((void**)&ctx16,   g_ctx16);
    cudaGetSymbolAddress((void**)&t1,      g_t1);
    cudaGetSymbolAddress((void**)&attn,    g_attn);
    cudaGetSymbolAddress((void**)&attn16,  g_attn16);
    cudaGetSymbolAddress((void**)&inter16, g_inter16);
    cudaGetSymbolAddress((void**)&t2,      g_t2);
    cudaGetSymbolAddress((void**)&hs16,    g_hs16);
    cudaGetSymbolAddress((void**)&wqt,     g_wqt);
    cudaGetSymbolAddress((void**)&wkt,     g_wkt);
    cudaGetSymbolAddress((void**)&wvt,     g_wvt);
    cudaGetSymbolAddress((void**)&wot,     g_wot);
    cudaGetSymbolAddress((void**)&wit,     g_wit);
    cudaGetSymbolAddress((void**)&wdt,     g_wdt);

    cudaFuncSetAttribute(flash_attn_kernel,
                         cudaFuncAttributeMaxDynamicSharedMemorySize, FLASH_SMEM);
    cudaFuncSetAttribute(hgemm_kernel<MODE_QKV>,
                         cudaFuncAttributeMaxDynamicSharedMemorySize, HGEMM_SMEM);
    cudaFuncSetAttribute(hgemm_kernel<MODE_RES>,
                         cudaFuncAttributeMaxDynamicSharedMemorySize, HGEMM_SMEM);
    cudaFuncSetAttribute(hgemm_kernel<MODE_GELU>,
                         cudaFuncAttributeMaxDynamicSharedMemorySize, HGEMM_SMEM);

    // ---- prep: hs fp16 copy + transposed fp16 weights ----
    {
        const int n = MROWS * HIDDIM;
        f2h_kernel<<<(n / 4 + 255) / 256, 256>>>(hs, hs16, n);
    }
    {
        TransArgs ta;
        ta.src[0] = Wq; ta.src[1] = Wk; ta.src[2] = Wv; ta.src[3] = Wo;
        ta.dst[0] = wqt; ta.dst[1] = wkt; ta.dst[2] = wvt; ta.dst[3] = wot;
        transpose_kernel<<<dim3(HIDDIM/32, HIDDIM/32, 4), 256>>>(ta, HIDDIM, HIDDIM);
    }
    {
        TransArgs ta = {};
        ta.src[0] = Wi; ta.dst[0] = wit;
        transpose_kernel<<<dim3(INTERDIM/32, HIDDIM/32, 1), 256>>>(ta, HIDDIM, INTERDIM);
    }
    {
        TransArgs ta = {};
        ta.src[0] = Wd; ta.dst[0] = wdt;
        transpose_kernel<<<dim3(HIDDIM/32, INTERDIM/32, 1), 256>>>(ta, INTERDIM, HIDDIM);
    }

    const int mblk = (MROWS + HBM - 1) / HBM;                    // 76

    // QKV fused: grid.z selects {q,k,v}; fp32 outputs in [B,H,S,DH]
    {
        GemmArgs ga;
        ga.W[0] = wqt; ga.W[1] = wkt; ga.W[2] = wvt;
        ga.bias[0] = bq; ga.bias[1] = bk; ga.bias[2] = bv;
        ga.out[0] = q; ga.out[1] = k; ga.out[2] = v;
        dim3 grid(mblk, HIDDIM / HBN, 3);                        // 76 x 6 x 3
        hgemm_kernel<MODE_QKV><<<grid, 256, HGEMM_SMEM>>>(hs16, ga, nullptr, HIDDIM, HIDDIM);
    }

    // attention -> ctx16 [B,S,HID] (fp16)
    dim3 gAtt((SEQ + AQT - 1) / AQT, NHEAD, BATCH);              // 10 x 12 x 8
    flash_attn_kernel<<<gAtt, 256, FLASH_SMEM>>>(q, k, v, amask, ctx16);

    // O-proj + residual, then LN1 (dual fp32/fp16 out)
    {
        GemmArgs ga = {};
        ga.W[0] = wot; ga.bias[0] = bo; ga.out[0] = t1;
        dim3 grid(mblk, HIDDIM / HBN, 1);
        hgemm_kernel<MODE_RES><<<grid, 256, HGEMM_SMEM>>>(ctx16, ga, hs, HIDDIM, HIDDIM);
    }
    layernorm_kernel<<<MROWS, 256>>>(t1, g1, b1, attn, attn16);

    // FFN
    {
        GemmArgs ga = {};
        ga.W[0] = wit; ga.bias[0] = bi; ga.out[0] = inter16;
        dim3 grid(mblk, INTERDIM / HBN, 1);
        hgemm_kernel<MODE_GELU><<<grid, 256, HGEMM_SMEM>>>(attn16, ga, nullptr, HIDDIM, INTERDIM);
    }
    {
        GemmArgs ga = {};
        ga.W[0] = wdt; ga.bias[0] = bd; ga.out[0] = t2;
        dim3 grid(mblk, HIDDIM / HBN, 1);
        hgemm_kernel<MODE_RES><<<grid, 256, HGEMM_SMEM>>>(inter16, ga, attn, INTERDIM, HIDDIM);
    }
    layernorm_kernel<<<MROWS, 256>>>(t2, g2, b2, out, nullptr);
}

// round 17
// speedup vs baseline: 1.0038x; 1.0038x over previous
#include <cuda_runtime.h>
#include <cuda_fp16.h>
#include <math.h>
#include <stdint.h>

#define BATCH 8
#define SEQ 1213
#define NHEAD 12
#define DHEAD 64
#define HIDDIM 768
#define INTERDIM 3072
#define MROWS (BATCH*SEQ)      // 9704
#define NLEAD 12

// ---------------- scratch (static device globals; no allocation allowed) ----
__device__ float  g_q[(size_t)BATCH*NHEAD*SEQ*DHEAD];
__device__ float  g_k[(size_t)BATCH*NHEAD*SEQ*DHEAD];
__device__ float  g_v[(size_t)BATCH*NHEAD*SEQ*DHEAD];
__device__ __half g_ctx16[(size_t)MROWS*HIDDIM];
__device__ float  g_t1[(size_t)MROWS*HIDDIM];
__device__ float  g_attn[(size_t)MROWS*HIDDIM];
__device__ __half g_attn16[(size_t)MROWS*HIDDIM];
__device__ __half g_inter16[(size_t)MROWS*INTERDIM];
__device__ float  g_t2[(size_t)MROWS*HIDDIM];
__device__ __half g_hs16[(size_t)MROWS*HIDDIM];
// transposed fp16 weights [N][K]
__device__ __half g_wqt[(size_t)HIDDIM*HIDDIM];
__device__ __half g_wkt[(size_t)HIDDIM*HIDDIM];
__device__ __half g_wvt[(size_t)HIDDIM*HIDDIM];
__device__ __half g_wot[(size_t)HIDDIM*HIDDIM];
__device__ __half g_wit[(size_t)INTERDIM*HIDDIM];
__device__ __half g_wdt[(size_t)HIDDIM*INTERDIM];

// ---------------- helpers ----------------------------------------------------
__device__ __forceinline__ void mma_tf32(float* c, const unsigned* a, const unsigned* b) {
    asm("mma.sync.aligned.m16n8k8.row.col.f32.tf32.tf32.f32 "
        "{%0,%1,%2,%3}, {%4,%5,%6,%7}, {%8,%9}, {%0,%1,%2,%3};"
        : "+f"(c[0]), "+f"(c[1]), "+f"(c[2]), "+f"(c[3])
        : "r"(a[0]), "r"(a[1]), "r"(a[2]), "r"(a[3]), "r"(b[0]), "r"(b[1]));
}
__device__ __forceinline__ void mma_f16(float* c, const unsigned* a, const unsigned* b) {
    asm("mma.sync.aligned.m16n8k16.row.col.f32.f16.f16.f32 "
        "{%0,%1,%2,%3}, {%4,%5,%6,%7}, {%8,%9}, {%0,%1,%2,%3};"
        : "+f"(c[0]), "+f"(c[1]), "+f"(c[2]), "+f"(c[3])
        : "r"(a[0]), "r"(a[1]), "r"(a[2]), "r"(a[3]), "r"(b[0]), "r"(b[1]));
}
__device__ __forceinline__ void ldsm_x4(unsigned& r0, unsigned& r1, unsigned& r2,
                                        unsigned& r3, uint32_t addr) {
    asm volatile("ldmatrix.sync.aligned.m8n8.x4.shared.b16 {%0,%1,%2,%3}, [%4];"
                 : "=r"(r0), "=r"(r1), "=r"(r2), "=r"(r3) : "r"(addr));
}
__device__ __forceinline__ uint32_t smem_u32(const void* p) {
    return (uint32_t)__cvta_generic_to_shared(p);
}
__device__ __forceinline__ void cp16(uint32_t dst, const void* src, int src_bytes) {
    asm volatile("cp.async.cg.shared.global [%0], [%1], 16, %2;"
                 :: "r"(dst), "l"(src), "r"(src_bytes) : "memory");
}
#define CP_COMMIT() asm volatile("cp.async.commit_group;" ::: "memory")
#define CP_WAIT1()  asm volatile("cp.async.wait_group 1;" ::: "memory")
#define CP_WAIT0()  asm volatile("cp.async.wait_group 0;" ::: "memory")

// ============================================================================
// fp32 -> fp16 convert (n multiple of 4)
// ============================================================================
__global__ __launch_bounds__(256)
void f2h_kernel(const float* __restrict__ x, __half* __restrict__ y, int n)
{
    const int i = (blockIdx.x * 256 + threadIdx.x) * 4;
    if (i < n) {
        const float4 v = *reinterpret_cast<const float4*>(x + i);
        __half2* yp = reinterpret_cast<__half2*>(y + i);
        yp[0] = __floats2half2_rn(v.x, v.y);
        yp[1] = __floats2half2_rn(v.z, v.w);
    }
}

// ============================================================================
// Weight transpose + fp16 convert: dst[c][r] = (half)src[r][c]
// ============================================================================
struct TransArgs { const float* src[4]; __half* dst[4]; };

__global__ __launch_bounds__(256)
void transpose_kernel(TransArgs ta, int R, int C)
{
    __shared__ float t[32][33];
    const float* src = ta.src[blockIdx.z];
    __half* dst = ta.dst[blockIdx.z];
    const int bx = blockIdx.x * 32, by = blockIdx.y * 32;
    const int tx = threadIdx.x & 31, ty = threadIdx.x >> 5;  // 32 x 8
#pragma unroll
    for (int i = ty; i < 32; i += 8)
        t[i][tx] = src[(size_t)(by + i) * C + bx + tx];
    __syncthreads();
#pragma unroll
    for (int i = ty; i < 32; i += 8)
        dst[(size_t)(bx + i) * R + by + tx] = __float2half_rn(t[tx][i]);
}

// ============================================================================
// FP16 tensor-core GEMM: C[M,N] = A16[M,K] @ Wt16[N,K]^T (+epilogue)
// BM=BN=128, BK=32, 256 threads (8 warps 2x4), warp tile 64x32,
// mma.m16n8k16 f16/f32-acc, ldmatrix fragment loads, 3-stage cp.async ring.
// SMEM tiles: A [128 rows][40 halves] (80B stride, ldmatrix conflict-free),
//             B [128 rows][40 halves]; one stage = 20480 B.
// ============================================================================
#define HBM 128
#define HBN 128
#define HBK 32
#define HSTRIDE_B 80            // bytes per smem row
#define HTILE_B (128*HSTRIDE_B) // 10240
#define HSTAGE_B (2*HTILE_B)    // 20480 (A then B)
#define HSTAGES 3
#define HGEMM_SMEM (HSTAGES*HSTAGE_B)   // 61440

enum { MODE_QKV = 0, MODE_RES = 1, MODE_GELU = 2 };

struct GemmArgs {
    const __half* W[3];     // transposed fp16 weights [N][K]
    const float*  bias[3];
    void*         out[3];   // float* (QKV/RES) or __half* (GELU)
};

template<int MODE>
__global__ __launch_bounds__(256, 2)
void hgemm_kernel(const __half* __restrict__ A, GemmArgs ga,
                  const float* __restrict__ Rsd, int K, int N)
{
    extern __shared__ char smc[];
    const uint32_t sb = smem_u32(smc);

    const int tid  = threadIdx.x;
    const int warp = tid >> 5;
    const int lane = tid & 31;
    const int wm   = warp >> 2;        // 0..1
    const int wn   = warp & 3;         // 0..3
    const int g    = lane >> 2;
    const int t4   = lane & 3;
    const int m0   = blockIdx.x * HBM;
    const int n0   = blockIdx.y * HBN;
    const int z    = blockIdx.z;

    const __half* W    = ga.W[z];
    const float*  bias = ga.bias[z];

    float acc[4][4][4];
#pragma unroll
    for (int i = 0; i < 4; i++)
#pragma unroll
        for (int j = 0; j < 4; j++)
#pragma unroll
            for (int r = 0; r < 4; r++) acc[i][j][r] = 0.f;

    // stage one K-chunk: A 128x32 halves + B 128x32 halves
    auto stage = [&](int kt, int s) {
        const int k0 = kt * HBK;
        const uint32_t ab = sb + s * HSTAGE_B;
        const uint32_t bb = ab + HTILE_B;
#pragma unroll
        for (int p = 0; p < 2; p++) {
            const int idx = tid + p * 256;      // 512 granules per tile
            const int r = idx >> 2, cq = idx & 3;
            cp16(ab + r * HSTRIDE_B + cq * 16,
                 A + (size_t)(m0 + r) * K + k0 + cq * 8, (m0 + r < MROWS) ? 16 : 0);
            cp16(bb + r * HSTRIDE_B + cq * 16,
                 W + (size_t)(n0 + r) * K + k0 + cq * 8, 16);
        }
    };

    const int nkt = K / HBK;           // 24 or 96
    stage(0, 0); CP_COMMIT();
    stage(1, 1); CP_COMMIT();

    // per-lane ldmatrix offsets
    // A: matrices (rows +0-7, k-lo), (rows +8-15, k-lo), (rows +0-7, k-hi), (+8-15, k-hi)
    const uint32_t aoff = (uint32_t)(wm * 64 + ((lane >> 3) & 1) * 8 + (lane & 7)) * HSTRIDE_B
                        + ((lane >> 4) & 1) * 16;
    // B: matrices (j0, k-lo), (j0, k-hi), (j1, k-lo), (j1, k-hi); rows = n
    const int bm = lane >> 3;          // 0..3
    const uint32_t boff = (uint32_t)(wn * 32 + (bm >> 1) * 8 + (lane & 7)) * HSTRIDE_B
                        + (bm & 1) * 16;

    int buf = 0;
    for (int kt = 0; kt < nkt; kt++) {
        CP_WAIT1();
        __syncthreads();
        if (kt + 2 < nkt) stage(kt + 2, (kt + 2) % HSTAGES);
        CP_COMMIT();

        const uint32_t ab = sb + buf * HSTAGE_B;
        const uint32_t bb = ab + HTILE_B;

#pragma unroll
        for (int kk = 0; kk < 2; kk++) {       // two k16 chunks (byte offset kk*32)
            unsigned a[4][4], b[4][2];
#pragma unroll
            for (int i = 0; i < 4; i++)
                ldsm_x4(a[i][0], a[i][1], a[i][2], a[i][3],
                        ab + aoff + i * (16 * HSTRIDE_B) + kk * 32);
            ldsm_x4(b[0][0], b[0][1], b[1][0], b[1][1], bb + boff + kk * 32);
            ldsm_x4(b[2][0], b[2][1], b[3][0], b[3][1],
                    bb + boff + 16 * HSTRIDE_B + kk * 32);
#pragma unroll
            for (int i = 0; i < 4; i++)
#pragma unroll
                for (int j = 0; j < 4; j++)
                    mma_f16(acc[i][j], a[i], b[j]);
        }
        buf = (buf + 1 == HSTAGES) ? 0 : buf + 1;
    }

    // ---- epilogue ----
#pragma unroll
    for (int i = 0; i < 4; i++) {
#pragma unroll
        for (int rr = 0; rr < 2; rr++) {
            const int m = m0 + wm * 64 + i * 16 + g + rr * 8;
            if (m >= MROWS) continue;
#pragma unroll
            for (int j = 0; j < 4; j++) {
                const int n = n0 + wn * 32 + j * 8 + t4 * 2;
                const float2 b2 = *reinterpret_cast<const float2*>(bias + n);
                const float x0 = acc[i][j][rr * 2 + 0] + b2.x;
                const float x1 = acc[i][j][rr * 2 + 1] + b2.y;

                if (MODE == MODE_QKV) {
                    float* out = (float*)ga.out[z];
                    const int h = n >> 6, d = n & 63;
                    const int bb2 = m / SEQ, srow = m % SEQ;
                    *reinterpret_cast<float2*>(
                        out + (((size_t)bb2 * NHEAD + h) * SEQ + srow) * DHEAD + d) =
                        make_float2(x0, x1);
                } else if (MODE == MODE_RES) {
                    float* out = (float*)ga.out[z];
                    const float2 r2 = *reinterpret_cast<const float2*>(Rsd + (size_t)m * N + n);
                    *reinterpret_cast<float2*>(out + (size_t)m * N + n) =
                        make_float2(x0 + r2.x, x1 + r2.y);
                } else {    // MODE_GELU -> fp16 output
                    __half* out = (__half*)ga.out[z];
                    float o0 = 0.5f * x0 * (1.f + erff(x0 * 0.70710678118654752f));
                    float o1 = 0.5f * x1 * (1.f + erff(x1 * 0.70710678118654752f));
                    *reinterpret_cast<__half2*>(out + (size_t)m * N + n) =
                        __floats2half2_rn(o0, o1);
                }
            }
        }
    }
}

// ============================================================================
// Flash attention: tf32 mma.sync (unchanged numerics from R9);
// epilogue writes fp16 ctx for the O-projection.
// ============================================================================
#define AQT 128
#define AKT 64
#define KPAD 68
#define VPAD 72
#define PPAD 68
#define FLASH_SMEM ((2*AKT*KPAD + 2*AKT*VPAD + AQT*PPAD) * 4)   // 106496

__global__ __launch_bounds__(256, 2)
void flash_attn_kernel(const float* __restrict__ Q, const float* __restrict__ Kg,
                       const float* __restrict__ Vg, const float* __restrict__ amask,
                       __half* __restrict__ ctx)
{
    extern __shared__ float sm[];
    float* sK = sm;                        // [2][64][KPAD]
    float* sV = sK + 2 * AKT * KPAD;       // [2][64][VPAD]
    float* sP = sV + 2 * AKT * VPAD;       // [128][PPAD]

    const int tid  = threadIdx.x;
    const int warp = tid >> 5;
    const int lane = tid & 31;
    const int g    = lane >> 2;
    const int t4   = lane & 3;
    const int qb   = warp * 16;
    const int q0   = blockIdx.x * AQT;
    const int h    = blockIdx.y;
    const int b    = blockIdx.z;
    const size_t base = ((size_t)b * NHEAD + h) * SEQ * DHEAD;

#pragma unroll
    for (int p = 0; p < 8; p++) {
        const int row = (tid >> 4) + p * 16;
        const int col = (tid & 15) * 4;
        float4 v = make_float4(0.f, 0.f, 0.f, 0.f);
        if (q0 + row < SEQ)
            v = *reinterpret_cast<const float4*>(Q + base + (size_t)(q0 + row) * DHEAD + col);
        *reinterpret_cast<float4*>(&sP[row * PPAD + col]) = v;
    }
    __syncthreads();

    unsigned qf[8][4];
#pragma unroll
    for (int kk = 0; kk < 8; kk++) {
        const float* qr = &sP[(qb + g) * PPAD + kk * 8 + t4];
        qf[kk][0] = __float_as_uint(qr[0]);
        qf[kk][1] = __float_as_uint(qr[8 * PPAD]);
        qf[kk][2] = __float_as_uint(qr[4]);
        qf[kk][3] = __float_as_uint(qr[8 * PPAD + 4]);
    }

    float m_run[2] = {-1e30f, -1e30f};
    float l_run[2] = {0.f, 0.f};
    float o[8][4];
#pragma unroll
    for (int j = 0; j < 8; j++)
#pragma unroll
        for (int r = 0; r < 4; r++) o[j][r] = 0.f;

    const bool lead_warp = (q0 == 0 && warp == 0);
    const int nkt = (SEQ + AKT - 1) / AKT;   // 19

    auto stageKV = [&](int kt, int buf) {
        const int k0 = kt * AKT;
        float* Kb = sK + buf * AKT * KPAD;
        float* Vb = sV + buf * AKT * VPAD;
#pragma unroll
        for (int p = 0; p < 4; p++) {
            const int s = tid + p * 256;
            const int row = s >> 4, c = (s & 15) * 4;
            const int sz = (k0 + row < SEQ) ? 16 : 0;
            const size_t off = base + (size_t)(k0 + row) * DHEAD + c;
            cp16(smem_u32(Kb + row * KPAD + c), Kg + off, sz);
            cp16(smem_u32(Vb + row * VPAD + c), Vg + off, sz);
        }
    };

    stageKV(0, 0); CP_COMMIT();

    for (int kt = 0; kt < nkt; kt++) {
        const int k0 = kt * AKT;
        const int buf = kt & 1;
        CP_WAIT0();
        __syncthreads();

        if (kt + 1 < nkt) stageKV(kt + 1, buf ^ 1);
        CP_COMMIT();

        const float* Kb = sK + buf * AKT * KPAD;
        const float* Vb = sV + buf * AKT * VPAD;

        float sc[8][4];
#pragma unroll
        for (int j = 0; j < 8; j++)
#pragma unroll
            for (int r = 0; r < 4; r++) sc[j][r] = 0.f;

#pragma unroll
        for (int kk = 0; kk < 8; kk++) {
#pragma unroll
            for (int j = 0; j < 8; j++) {
                unsigned bb[2];
                const float* kr = &Kb[(j * 8 + g) * KPAD + kk * 8 + t4];
                bb[0] = __float_as_uint(kr[0]);
                bb[1] = __float_as_uint(kr[4]);
                mma_tf32(sc[j], qf[kk], bb);
            }
        }

#pragma unroll
        for (int j = 0; j < 8; j++) {
#pragma unroll
            for (int e = 0; e < 2; e++) {
                const int cg = k0 + j * 8 + 2 * t4 + e;
                const float am = (cg < SEQ) ? __ldg(amask + (size_t)b * SEQ + cg) : 0.f;
#pragma unroll
                for (int rr = 0; rr < 2; rr++) {
                    float val = fmaf(sc[j][rr * 2 + e], 0.125f, am);
                    if (cg >= SEQ) val = -1e30f;
                    if (lead_warp) {
                        const int qg = qb + g + rr * 8;
                        if (qg == 0) {
                            if (cg >= 1 && cg < 1 + NLEAD) val -= 99999.f;
                        } else if (qg >= 1 && qg <= NLEAD) {
                            const int start = NLEAD + 1 + 100 * (qg - 1);
                            if (!(cg >= start && cg < start + 100)) val -= 99999.f;
                        }
                    }
                    sc[j][rr * 2 + e] = val;
                }
            }
        }

#pragma unroll
        for (int rr = 0; rr < 2; rr++) {
            float mt = -1e30f;
#pragma unroll
            for (int j = 0; j < 8; j++)
                mt = fmaxf(mt, fmaxf(sc[j][rr * 2], sc[j][rr * 2 + 1]));
            mt = fmaxf(mt, __shfl_xor_sync(0xffffffffu, mt, 1));
            mt = fmaxf(mt, __shfl_xor_sync(0xffffffffu, mt, 2));
            const float mnew = fmaxf(m_run[rr], mt);
            const float fac = __expf(m_run[rr] - mnew);
            m_run[rr] = mnew;
            float ls = 0.f;
#pragma unroll
            for (int j = 0; j < 8; j++) {
                const float p0 = __expf(sc[j][rr * 2    ] - mnew);
                const float p1 = __expf(sc[j][rr * 2 + 1] - mnew);
                sc[j][rr * 2    ] = p0;
                sc[j][rr * 2 + 1] = p1;
                ls += p0 + p1;
            }
            ls += __shfl_xor_sync(0xffffffffu, ls, 1);
            ls += __shfl_xor_sync(0xffffffffu, ls, 2);
            l_run[rr] = l_run[rr] * fac + ls;
#pragma unroll
            for (int j = 0; j < 8; j++) {
                o[j][rr * 2    ] *= fac;
                o[j][rr * 2 + 1] *= fac;
            }
        }

#pragma unroll
        for (int rr = 0; rr < 2; rr++)
#pragma unroll
            for (int j = 0; j < 8; j++)
                *reinterpret_cast<float2*>(
                    &sP[(qb + g + rr * 8) * PPAD + j * 8 + 2 * t4]) =
                    make_float2(sc[j][rr * 2], sc[j][rr * 2 + 1]);
        __syncwarp();

#pragma unroll
        for (int kk = 0; kk < 8; kk++) {
            unsigned a[4];
            const float* pr = &sP[(qb + g) * PPAD + kk * 8 + t4];
            a[0] = __float_as_uint(pr[0]);
            a[1] = __float_as_uint(pr[8 * PPAD]);
            a[2] = __float_as_uint(pr[4]);
            a[3] = __float_as_uint(pr[8 * PPAD + 4]);
#pragma unroll
            for (int j = 0; j < 8; j++) {
                unsigned bb[2];
                const float* vr = &Vb[(kk * 8 + t4) * VPAD + j * 8 + g];
                bb[0] = __float_as_uint(vr[0]);
                bb[1] = __float_as_uint(vr[4 * VPAD]);
                mma_tf32(o[j], a, bb);
            }
        }
    }

    // ---- epilogue: normalize and write fp16 ctx [B,S,HID] ----
#pragma unroll
    for (int rr = 0; rr < 2; rr++) {
        const int qg = q0 + qb + g + rr * 8;
        if (qg < SEQ) {
            const float inv = 1.f / l_run[rr];
#pragma unroll
            for (int j = 0; j < 8; j++) {
                *reinterpret_cast<__half2*>(
                    ctx + ((size_t)b * SEQ + qg) * HIDDIM + h * DHEAD + j * 8 + 2 * t4) =
                    __floats2half2_rn(o[j][rr * 2] * inv, o[j][rr * 2 + 1] * inv);
            }
        }
    }
}

// ---------------- LayerNorm (fp32 out + optional fp16 copy) ------------------
__global__ __launch_bounds__(256)
void layernorm_kernel(const float* __restrict__ x, const float* __restrict__ g,
                      const float* __restrict__ bb, float* __restrict__ y,
                      __half* __restrict__ y16)
{
    __shared__ float red[8];
    __shared__ float sMean, sRstd;
    const int row = blockIdx.x;
    const int tid = threadIdx.x;
    const float* xr = x + (size_t)row * HIDDIM;

    float v[3];
    float sum = 0.f;
#pragma unroll
    for (int i = 0; i < 3; i++) { v[i] = xr[tid + i * 256]; sum += v[i]; }

#pragma unroll
    for (int o = 16; o > 0; o >>= 1) sum += __shfl_down_sync(0xffffffffu, sum, o);
    if ((tid & 31) == 0) red[tid >> 5] = sum;
    __syncthreads();
    if (tid < 32) {
        float t = (tid < 8) ? red[tid] : 0.f;
#pragma unroll
        for (int o = 4; o > 0; o >>= 1) t += __shfl_down_sync(0xffffffffu, t, o);
        if (tid == 0) sMean = t * (1.f / HIDDIM);
    }
    __syncthreads();
    const float mean = sMean;

    float sq = 0.f;
#pragma unroll
    for (int i = 0; i < 3; i++) { float d = v[i] - mean; sq += d * d; }
#pragma unroll
    for (int o = 16; o > 0; o >>= 1) sq += __shfl_down_sync(0xffffffffu, sq, o);
    __syncthreads();
    if ((tid & 31) == 0) red[tid >> 5] = sq;
    __syncthreads();
    if (tid < 32) {
        float t = (tid < 8) ? red[tid] : 0.f;
#pragma unroll
        for (int o = 4; o > 0; o >>= 1) t += __shfl_down_sync(0xffffffffu, t, o);
        if (tid == 0) sRstd = rsqrtf(t * (1.f / HIDDIM) + 1e-12f);
    }
    __syncthreads();
    const float rstd = sRstd;

#pragma unroll
    for (int i = 0; i < 3; i++) {
        const int c = tid + i * 256;
        const float val = g[c] * (v[i] - mean) * rstd + bb[c];
        y[(size_t)row * HIDDIM + c] = val;
        if (y16) y16[(size_t)row * HIDDIM + c] = __float2half_rn(val);
    }
}

// ---------------- launch ----------------------------------------------------
extern "C" void kernel_launch(void* const* d_in, const int* in_sizes, int n_in,
                              void* d_out, int out_size)
{
    const float* hs    = (const float*)d_in[0];
    const float* amask = (const float*)d_in[1];
    const float* Wq = (const float*)d_in[2];  const float* bq = (const float*)d_in[3];
    const float* Wk = (const float*)d_in[4];  const float* bk = (const float*)d_in[5];
    const float* Wv = (const float*)d_in[6];  const float* bv = (const float*)d_in[7];
    const float* Wo = (const float*)d_in[8];  const float* bo = (const float*)d_in[9];
    const float* g1 = (const float*)d_in[10]; const float* b1 = (const float*)d_in[11];
    const float* Wi = (const float*)d_in[12]; const float* bi = (const float*)d_in[13];
    const float* Wd = (const float*)d_in[14]; const float* bd = (const float*)d_in[15];
    const float* g2 = (const float*)d_in[16]; const float* b2 = (const float*)d_in[17];
    float* out = (float*)d_out;

    float *q, *k, *v, *t1, *attn, *t2;
    __half *ctx16, *attn16, *inter16, *hs16;
    __half *wqt, *wkt, *wvt, *wot, *wit, *wdt;
    cudaGetSymbolAddress((void**)&q,       g_q);
    cudaGetSymbolAddress((void**)&k,       g_k);
    cudaGetSymbolAddress((void**)&v,       g_v);
    cudaGetSymbolAddress((void**)&ctx16,   g_ctx16);
    cudaGetSymbolAddress((void**)&t1,      g_t1);
    cudaGetSymbolAddress((void**)&attn,    g_attn);
    cudaGetSymbolAddress((void**)&attn16,  g_attn16);
    cudaGetSymbolAddress((void**)&inter16, g_inter16);
    cudaGetSymbolAddress((void**)&t2,      g_t2);
    cudaGetSymbolAddress((void**)&hs16,    g_hs16);
    cudaGetSymbolAddress((void**)&wqt,     g_wqt);
    cudaGetSymbolAddress((void**)&wkt,     g_wkt);
    cudaGetSymbolAddress((void**)&wvt,     g_wvt);
    cudaGetSymbolAddress((void**)&wot,     g_wot);
    cudaGetSymbolAddress((void**)&wit,     g_wit);
    cudaGetSymbolAddress((void**)&wdt,     g_wdt);

    cudaFuncSetAttribute(flash_attn_kernel,
                         cudaFuncAttributeMaxDynamicSharedMemorySize, FLASH_SMEM);
    cudaFuncSetAttribute(hgemm_kernel<MODE_QKV>,
                         cudaFuncAttributeMaxDynamicSharedMemorySize, HGEMM_SMEM);
    cudaFuncSetAttribute(hgemm_kernel<MODE_RES>,
                         cudaFuncAttributeMaxDynamicSharedMemorySize, HGEMM_SMEM);
    cudaFuncSetAttribute(hgemm_kernel<MODE_GELU>,
                         cudaFuncAttributeMaxDynamicSharedMemorySize, HGEMM_SMEM);

    // ---- prep: hs fp16 copy + transposed fp16 weights ----
    {
        const int n = MROWS * HIDDIM;
        f2h_kernel<<<(n / 4 + 255) / 256, 256>>>(hs, hs16, n);
    }
    {
        TransArgs ta;
        ta.src[0] = Wq; ta.src[1] = Wk; ta.src[2] = Wv; ta.src[3] = Wo;
        ta.dst[0] = wqt; ta.dst[1] = wkt; ta.dst[2] = wvt; ta.dst[3] = wot;
        transpose_kernel<<<dim3(HIDDIM/32, HIDDIM/32, 4), 256>>>(ta, HIDDIM, HIDDIM);
    }
    {
        TransArgs ta = {};
        ta.src[0] = Wi; ta.dst[0] = wit;
        transpose_kernel<<<dim3(INTERDIM/32, HIDDIM/32, 1), 256>>>(ta, HIDDIM, INTERDIM);
    }
    {
        TransArgs ta = {};
        ta.src[0] = Wd; ta.dst[0] = wdt;
        transpose_kernel<<<dim3(HIDDIM/32, INTERDIM/32, 1), 256>>>(ta, INTERDIM, HIDDIM);
    }

    const int mblk = (MROWS + HBM - 1) / HBM;                    // 76

    // QKV fused: grid.z selects {q,k,v}; fp32 outputs in [B,H,S,DH]
    {
        GemmArgs ga;
        ga.W[0] = wqt; ga.W[1] = wkt; ga.W[2] = wvt;
        ga.bias[0] = bq; ga.bias[1] = bk; ga.bias[2] = bv;
        ga.out[0] = q; ga.out[1] = k; ga.out[2] = v;
        dim3 grid(mblk, HIDDIM / HBN, 3);                        // 76 x 6 x 3
        hgemm_kernel<MODE_QKV><<<grid, 256, HGEMM_SMEM>>>(hs16, ga, nullptr, HIDDIM, HIDDIM);
    }

    // attention -> ctx16 [B,S,HID] (fp16)
    dim3 gAtt((SEQ + AQT - 1) / AQT, NHEAD, BATCH);              // 10 x 12 x 8
    flash_attn_kernel<<<gAtt, 256, FLASH_SMEM>>>(q, k, v, amask, ctx16);

    // O-proj + residual, then LN1 (dual fp32/fp16 out)
    {
        GemmArgs ga = {};
        ga.W[0] = wot; ga.bias[0] = bo; ga.out[0] = t1;
        dim3 grid(mblk, HIDDIM / HBN, 1);
        hgemm_kernel<MODE_RES><<<grid, 256, HGEMM_SMEM>>>(ctx16, ga, hs, HIDDIM, HIDDIM);
    }
    layernorm_kernel<<<MROWS, 256>>>(t1, g1, b1, attn, attn16);

    // FFN
    {
        GemmArgs ga = {};
        ga.W[0] = wit; ga.bias[0] = bi; ga.out[0] = inter16;
        dim3 grid(mblk, INTERDIM / HBN, 1);
        hgemm_kernel<MODE_GELU><<<grid, 256, HGEMM_SMEM>>>(attn16, ga, nullptr, HIDDIM, INTERDIM);
    }
    {
        GemmArgs ga = {};
        ga.W[0] = wdt; ga.bias[0] = bd; ga.out[0] = t2;
        dim3 grid(mblk, HIDDIM / HBN, 1);
        hgemm_kernel<MODE_RES><<<grid, 256, HGEMM_SMEM>>>(inter16, ga, attn, INTERDIM, HIDDIM);
    }
    layernorm_kernel<<<MROWS, 256>>>(t2, g2, b2, out, nullptr);
}